// round 13
// baseline (speedup 1.0000x reference)
#include <cuda_runtime.h>

#define VV   400000
#define DD   200
#define CC   45
#define BSN  4096      // B*S
#define SS   128       // S (window padding is per-sequence)
#define KN   12
#define KC   10
#define KT   22
#define F5   1000      // 5*D
#define KQ   250       // F5/4 float4 per window

// ---- kernel 2 tiling ----
#define TT    32       // tokens per block (128 blocks; 32 divides 128)
#define CPAD  48
#define WF4   256      // W row stride in float4 (4096B)
#define XF4   50       // X row stride in float4 = DD/4 (windows stay contiguous!)
#define NT2   768      // 24 warps: 6 c-groups x 4 t-octets; lane = 8 ks x 4 tg

// scratch: feat [4096, 200]
__device__ float g_feat[BSN * DD];

// ============================================================
// Kernel 1: masked gather + mean  -> g_feat
// ============================================================
__global__ __launch_bounds__(128) void feat_kernel(
    const int* __restrict__ ng_ids, const int* __restrict__ ng_mask,
    const int* __restrict__ cx_ids, const int* __restrict__ cx_mask,
    const float* __restrict__ embed)
{
    const int tok = blockIdx.x;
    const int tid = threadIdx.x;

    __shared__ int raw_ids[KT], raw_msk[KT];
    __shared__ int s_ids[KT];
    __shared__ int s_n;
    __shared__ float s_inv;

    if (tid < KN) {
        raw_ids[tid] = ng_ids[tok * KN + tid];
        raw_msk[tid] = ng_mask[tok * KN + tid];
    } else if (tid < KT) {
        const int j = tid - KN;
        raw_ids[tid] = cx_ids[tok * KC + j];
        raw_msk[tid] = cx_mask[tok * KC + j];
    }
    __syncthreads();

    if (tid == 0) {
        int n = 0;
        #pragma unroll
        for (int i = 0; i < KT; i++)
            if (raw_msk[i]) s_ids[n++] = raw_ids[i];
        s_n = n;
        s_inv = 1.0f / (float)(n > 0 ? n : 1);
    }
    __syncthreads();

    const int n = s_n;
    const float inv = s_inv;

    if (tid < DD / 2) {
        float sx = 0.f, sy = 0.f;
        #pragma unroll 4
        for (int i = 0; i < n; i++) {
            const long long row = (long long)s_ids[i] * DD;
            const float2 v = *(const float2*)&embed[row + tid * 2];
            sx += v.x; sy += v.y;
        }
        *(float2*)&g_feat[(long long)tok * DD + tid * 2] = make_float2(sx * inv, sy * inv);
    }
}

// ============================================================
// Kernel 2: windowed matmul, 24 warps/SM
//   warp = 8 ks-lanes x 4 t-groups; thread tile = 8c x 2t
//   w LDS.128: 8 consecutive f4, 4-way broadcast -> 1 phase
//   x LDS.128: addr mod 8 = (4g+2i+ks)%8 -> exact 4-phase floor
//   Window for local token t = 250 contiguous f4 at sX[t*50] (halo rows 0-1).
// ============================================================
__device__ __forceinline__ void ffma2(unsigned long long& d,
                                      unsigned long long a,
                                      unsigned long long b)
{
    asm volatile("fma.rn.f32x2 %0, %1, %2, %0;" : "+l"(d) : "l"(a), "l"(b));
}

extern __shared__ float smem2[];

__global__ __launch_bounds__(NT2, 1) void gemm_kernel(
    const float* __restrict__ W, const float* __restrict__ bias,
    float* __restrict__ out)
{
    float* sW = smem2;                        // CPAD * WF4 float4
    float* sX = smem2 + CPAD * WF4 * 4;       // 36 rows * XF4 float4

    const int tid = threadIdx.x;
    const int t0  = blockIdx.x * TT;
    const int b0  = t0 / SS;                  // sequence index of this tile

    // ---- fill W: [48 rows x 256 f4], zero-padded ----
    {
        float4*       sW4 = (float4*)sW;
        const float4* W4  = (const float4*)W;           // [45, 250] f4
        #pragma unroll
        for (int it = 0; it < (CPAD * WF4) / NT2; it++) {   // 16 iters
            const int i   = it * NT2 + tid;
            const int row = i >> 8;
            const int q   = i & (WF4 - 1);
            float4 v = make_float4(0.f, 0.f, 0.f, 0.f);
            if (row < CC && q < KQ) v = W4[row * KQ + q];
            sW4[i] = v;
        }
    }

    // ---- fill X tile (+-2 halo rows), zero outside this sequence ----
    {
        float4*       sX4   = (float4*)sX;
        const float4* feat4 = (const float4*)g_feat;
        for (int i = tid; i < 36 * XF4; i += NT2) {         // 1800 f4
            const int row = i / XF4;
            const int col = i - row * XF4;
            const int g   = t0 + row - 2;
            const bool ok = ((g >> 7) == b0);            // same sequence only
            sX4[i] = ok ? feat4[(long long)g * XF4 + col]
                        : make_float4(0.f, 0.f, 0.f, 0.f);
        }
    }
    __syncthreads();

    // ---- decomposition: 24 warps = 6 cg x 4 th; lane = 8 ks x 4 tg ----
    const int lane = tid & 31;
    const int wrp  = tid >> 5;        // 0..23
    const int ks   = lane & 7;        // k-split lane (f4 chunks ks + 8s)
    const int g    = lane >> 3;       // t-group, 0..3
    const int cg   = wrp % 6;         // c group (8 c's)
    const int th   = wrp / 6;         // token octet, 0..3
    const int cbase  = cg * 8;
    const int ltbase = th * 8 + g * 2;   // thread tokens: ltbase, ltbase+1

    unsigned long long acc[2][8];
    #pragma unroll
    for (int i = 0; i < 2; i++)
        #pragma unroll
        for (int j = 0; j < 8; j++) acc[i][j] = 0ull;

    const ulonglong2* wp = (const ulonglong2*)sW + (long long)cbase * WF4 + ks;
    const ulonglong2* xp = (const ulonglong2*)sX + (long long)ltbase * XF4 + ks;

    const int len = (KQ - ks + 7) >> 3;          // 32 for ks<2, else 31

    #pragma unroll 1
    for (int s = 0; s < len; s++) {
        const int q = s * 8;
        ulonglong2 x[2];
        #pragma unroll
        for (int i = 0; i < 2; i++) x[i] = xp[i * XF4 + q];

        ulonglong2 w[4];
        #pragma unroll
        for (int j = 0; j < 4; j++) w[j] = wp[j * WF4 + q];
        #pragma unroll
        for (int i = 0; i < 2; i++)
            #pragma unroll
            for (int j = 0; j < 4; j++) {
                ffma2(acc[i][j], x[i].x, w[j].x);
                ffma2(acc[i][j], x[i].y, w[j].y);
            }

        #pragma unroll
        for (int j = 0; j < 4; j++) w[j] = wp[(j + 4) * WF4 + q];
        #pragma unroll
        for (int i = 0; i < 2; i++)
            #pragma unroll
            for (int j = 0; j < 4; j++) {
                ffma2(acc[i][j + 4], x[i].x, w[j].x);
                ffma2(acc[i][j + 4], x[i].y, w[j].y);
            }
    }

    // ---- reduce packed halves + across 8 ks lanes ----
    #pragma unroll
    for (int i = 0; i < 2; i++) {
        #pragma unroll
        for (int j = 0; j < 8; j++) {
            const unsigned long long a = acc[i][j];
            float v = __uint_as_float((unsigned)(a & 0xffffffffull)) +
                      __uint_as_float((unsigned)(a >> 32));
            v += __shfl_xor_sync(0xffffffffu, v, 1);
            v += __shfl_xor_sync(0xffffffffu, v, 2);
            v += __shfl_xor_sync(0xffffffffu, v, 4);
            if (ks == 0) {
                const int c = cbase + j;
                if (c < CC) {
                    const int t = t0 + ltbase + i;
                    out[(long long)t * CC + c] = v + bias[c];
                }
            }
        }
    }
}

// ============================================================
extern "C" void kernel_launch(void* const* d_in, const int* in_sizes, int n_in,
                              void* d_out, int out_size)
{
    const int*   ng_ids  = (const int*)d_in[0];
    const int*   ng_mask = (const int*)d_in[1];
    const int*   cx_ids  = (const int*)d_in[2];
    const int*   cx_mask = (const int*)d_in[3];
    const float* embed   = (const float*)d_in[4];
    const float* W       = (const float*)d_in[5];
    const float* bias    = (const float*)d_in[6];
    float*       out     = (float*)d_out;

    feat_kernel<<<BSN, 128>>>(ng_ids, ng_mask, cx_ids, cx_mask, embed);

    const size_t smem = (size_t)(CPAD * WF4 * 4 + 36 * XF4 * 4) * sizeof(float); // 225,408 B
    cudaFuncSetAttribute(gemm_kernel, cudaFuncAttributeMaxDynamicSharedMemorySize, (int)smem);
    gemm_kernel<<<BSN / TT, NT2, smem>>>(W, bias, out);
}

// round 14
// speedup vs baseline: 1.0169x; 1.0169x over previous
#include <cuda_runtime.h>

#define VV   400000
#define DD   200
#define CC   45
#define BSN  4096      // B*S
#define SS   128       // S (window padding is per-sequence)
#define KN   12
#define KC   10
#define KT   22
#define F5   1000      // 5*D
#define KQ   250       // F5/4 float4 per window

// ---- kernel 2 config ----
#define TT    32       // tokens per block (grid 128)
#define WS4   251      // sW row stride in float4 (250 data + 1 zero pad col)
#define NT2   256      // 8 warps: warp = k-slice, lane = token

// scratch: feat [4096, 200]
__device__ float g_feat[BSN * DD];

// ============================================================
// Kernel 1: masked gather + mean  -> g_feat
// ============================================================
__global__ __launch_bounds__(128) void feat_kernel(
    const int* __restrict__ ng_ids, const int* __restrict__ ng_mask,
    const int* __restrict__ cx_ids, const int* __restrict__ cx_mask,
    const float* __restrict__ embed)
{
    const int tok = blockIdx.x;
    const int tid = threadIdx.x;

    __shared__ int raw_ids[KT], raw_msk[KT];
    __shared__ int s_ids[KT];
    __shared__ int s_n;
    __shared__ float s_inv;

    if (tid < KN) {
        raw_ids[tid] = ng_ids[tok * KN + tid];
        raw_msk[tid] = ng_mask[tok * KN + tid];
    } else if (tid < KT) {
        const int j = tid - KN;
        raw_ids[tid] = cx_ids[tok * KC + j];
        raw_msk[tid] = cx_mask[tok * KC + j];
    }
    __syncthreads();

    if (tid == 0) {
        int n = 0;
        #pragma unroll
        for (int i = 0; i < KT; i++)
            if (raw_msk[i]) s_ids[n++] = raw_ids[i];
        s_n = n;
        s_inv = 1.0f / (float)(n > 0 ? n : 1);
    }
    __syncthreads();

    const int n = s_n;
    const float inv = s_inv;

    if (tid < DD / 2) {
        float sx = 0.f, sy = 0.f;
        #pragma unroll 4
        for (int i = 0; i < n; i++) {
            const long long row = (long long)s_ids[i] * DD;
            const float2 v = *(const float2*)&embed[row + tid * 2];
            sx += v.x; sy += v.y;
        }
        *(float2*)&g_feat[(long long)tok * DD + tid * 2] = make_float2(sx * inv, sy * inv);
    }
}

// ============================================================
// Kernel 2: windowed matmul, lane = token
//   x: each lane keeps its token's k-slice (<=128 floats) in registers,
//      loaded straight from g_feat (window is contiguous there), with
//      per-f4 sequence-boundary predication (per-seq zero padding).
//   W: uniform-address LDS.128 -> HW broadcast, 1 wavefront, no conflicts.
//   k-reduce: partials staged in smem, folded in a short tail.
// ============================================================
__device__ __forceinline__ void ffma2(unsigned long long& d,
                                      unsigned long long a,
                                      unsigned long long b)
{
    asm volatile("fma.rn.f32x2 %0, %1, %2, %0;" : "+l"(d) : "l"(a), "l"(b));
}

extern __shared__ float smem2[];

__global__ __launch_bounds__(NT2, 1) void gemm_kernel(
    const float* __restrict__ W, const float* __restrict__ bias,
    float* __restrict__ out)
{
    float* sW = smem2;                        // 45 * WS4 float4
    float* sP = smem2 + CC * WS4 * 4;         // partials: [32 t][45 c][8 ks] floats

    const int tid  = threadIdx.x;
    const int t0   = blockIdx.x * TT;
    const int lane = tid & 31;                // token within tile
    const int ks   = tid >> 5;                // k-slice (warp id), 0..7

    // k-slices in f4: ks<2 -> 32 f4, else 31 f4 (sum = 250)
    const int q0  = (ks < 2) ? ks * 32 : 64 + (ks - 2) * 31;

    // ---- fill W into smem: [45][251] f4, col 250 zeroed ----
    {
        float4*       sW4 = (float4*)sW;
        const float4* W4  = (const float4*)W;            // [45][250] f4
        for (int i = tid; i < CC * WS4; i += NT2) {
            const int row = i / WS4;
            const int col = i - row * WS4;
            sW4[i] = (col < KQ) ? W4[row * KQ + col]
                                : make_float4(0.f, 0.f, 0.f, 0.f);
        }
    }

    // ---- load this lane's x k-slice into registers (from global) ----
    const int tg  = t0 + lane;                // global token
    const int seq = tg >> 7;                  // sequence index
    const float4* fbase = (const float4*)g_feat + ((long long)tg - 2) * (DD / 4);

    ulonglong2 x2[32];
    #pragma unroll
    for (int j = 0; j < 32; j++) {
        const int q   = q0 + j;
        const int r   = q / 50;               // feat-row offset within window
        const int row = tg - 2 + r;
        // valid: same sequence (handles tile edges), and j=31 only for ks<2
        const bool ok = ((row >> 7) == seq) && (j < 31 || ks < 2);
        float4 v = make_float4(0.f, 0.f, 0.f, 0.f);
        if (ok) v = __ldg(fbase + q);
        x2[j] = *(ulonglong2*)&v;
    }
    __syncthreads();

    // ---- main loop: 9 chunks of 5 c's; W loads are pure broadcast ----
    const ulonglong2* sW2 = (const ulonglong2*)sW;       // row stride WS4
    #pragma unroll 1
    for (int cq = 0; cq < 9; cq++) {
        const int cb = cq * 5;
        unsigned long long a0 = 0, a1 = 0, a2 = 0, a3 = 0, a4 = 0;
        const ulonglong2* wp = sW2 + (long long)cb * WS4 + q0;

        #pragma unroll
        for (int j = 0; j < 32; j++) {
            const ulonglong2 w0 = wp[0 * WS4 + j];
            const ulonglong2 w1 = wp[1 * WS4 + j];
            const ulonglong2 w2 = wp[2 * WS4 + j];
            const ulonglong2 w3 = wp[3 * WS4 + j];
            const ulonglong2 w4 = wp[4 * WS4 + j];
            const unsigned long long xa = x2[j].x, xb = x2[j].y;
            ffma2(a0, xa, w0.x);  ffma2(a0, xb, w0.y);
            ffma2(a1, xa, w1.x);  ffma2(a1, xb, w1.y);
            ffma2(a2, xa, w2.x);  ffma2(a2, xb, w2.y);
            ffma2(a3, xa, w3.x);  ffma2(a3, xb, w3.y);
            ffma2(a4, xa, w4.x);  ffma2(a4, xb, w4.y);
        }

        // fold packed halves, stage partials: sP[(lane*45 + c)*8 + ks]
        unsigned long long aa[5] = {a0, a1, a2, a3, a4};
        #pragma unroll
        for (int cc = 0; cc < 5; cc++) {
            const float v = __uint_as_float((unsigned)(aa[cc] & 0xffffffffull)) +
                            __uint_as_float((unsigned)(aa[cc] >> 32));
            sP[((lane * CC) + cb + cc) * 8 + ks] = v;
        }
    }
    __syncthreads();

    // ---- tail: 8-way k-reduce + bias + store ----
    for (int o = tid; o < TT * CC; o += NT2) {
        const float4* p = (const float4*)(sP + o * 8);
        const float4 a = p[0], b = p[1];
        const float v = ((a.x + a.y) + (a.z + a.w)) +
                        ((b.x + b.y) + (b.z + b.w));
        const int t = o / CC;
        const int c = o - t * CC;
        out[(long long)(t0 + t) * CC + c] = v + bias[c];
    }
}

// ============================================================
extern "C" void kernel_launch(void* const* d_in, const int* in_sizes, int n_in,
                              void* d_out, int out_size)
{
    const int*   ng_ids  = (const int*)d_in[0];
    const int*   ng_mask = (const int*)d_in[1];
    const int*   cx_ids  = (const int*)d_in[2];
    const int*   cx_mask = (const int*)d_in[3];
    const float* embed   = (const float*)d_in[4];
    const float* W       = (const float*)d_in[5];
    const float* bias    = (const float*)d_in[6];
    float*       out     = (float*)d_out;

    feat_kernel<<<BSN, 128>>>(ng_ids, ng_mask, cx_ids, cx_mask, embed);

    // 45*251*16 (W) + 32*45*8*4 (partials) = 180,720 + 46,080 = 226,800 B
    const size_t smem = (size_t)(CC * WS4 * 4 + TT * CC * 8) * sizeof(float);
    cudaFuncSetAttribute(gemm_kernel, cudaFuncAttributeMaxDynamicSharedMemorySize, (int)smem);
    gemm_kernel<<<BSN / TT, NT2, smem>>>(W, bias, out);
}